// round 9
// baseline (speedup 1.0000x reference)
#include <cuda_runtime.h>
#include <cstddef>

// RoiAlign: 4-level FPN, B=2, N=1000, C=256, POOL=7
// out[B, N, 7, 7, C] float32
//
// Two launches:
//  1) sort_kernel: counting-sort ROI indices by (batch, level, morton(center))
//  2) roi_align_kernel: 1 CTA/SM, consumes sorted ROIs in chunks of 4 so
//     consecutive (spatially adjacent) ROIs reuse the feature tiles in L1,
//     bypassing the LTS bandwidth cap that pins the naive kernel at ~39.4us.

#define POOL   7
#define C_CH   256
#define NPOS   (POOL * POOL)   // 49
#define NSM    148
#define CHUNK  4
#define NBUCKET 2048
#define MAXROI  4096

__device__ unsigned int g_order[MAXROI];
__device__ unsigned int g_ctr;

__device__ __forceinline__ unsigned morton8(unsigned y, unsigned x) {
    unsigned m = 0;
    #pragma unroll
    for (int i = 0; i < 4; i++) {
        m |= ((x >> i) & 1u) << (2 * i);
        m |= ((y >> i) & 1u) << (2 * i + 1);
    }
    return m;
}

__device__ __forceinline__ int level_of(float x1, float y1, float x2, float y2) {
    const float area  = (y2 - y1) * (x2 - x1);
    const float canon = 56.0f / 1024.0f + 1e-6f;
    const float lf = floorf(logf(sqrtf(area) / canon) / logf(2.0f));
    int lvl = 0;
    if (lf >= 3.0f)       lvl = 3;
    else if (lf >= 1.0f)  lvl = (int)lf;
    return lvl;
}

// ---------------- sort: single CTA counting sort over 2048 buckets ----------
__global__ __launch_bounds__(1024, 1)
void sort_kernel(const float* __restrict__ props, int BN, int N, unsigned ctr_init)
{
    __shared__ unsigned       cnt[NBUCKET];
    __shared__ unsigned short s_key[MAXROI];

    const int tid = threadIdx.x;

    for (int i = tid; i < NBUCKET; i += 1024) cnt[i] = 0;
    __syncthreads();

    for (int i = tid; i < BN; i += 1024) {
        const float4 box = reinterpret_cast<const float4*>(props)[i];
        const int lvl = level_of(box.x, box.y, box.z, box.w);
        const int b   = i / N;
        const float cx = 0.5f * (box.x + box.z);
        const float cy = 0.5f * (box.y + box.w);
        const unsigned txi = (unsigned)min(15, max(0, (int)(cx * 16.0f)));
        const unsigned tyi = (unsigned)min(15, max(0, (int)(cy * 16.0f)));
        const unsigned key = ((unsigned)(b & 1) << 10) | ((unsigned)lvl << 8)
                           | morton8(tyi, txi);
        s_key[i] = (unsigned short)key;
        atomicAdd(&cnt[key], 1u);
    }
    __syncthreads();

    // exclusive prefix sum over 2048 buckets: warp 0, 64 buckets per lane
    if (tid < 32) {
        const int base = tid * 64;
        unsigned sum = 0;
        for (int j = 0; j < 64; j++) sum += cnt[base + j];
        unsigned inc = sum;
        #pragma unroll
        for (int d = 1; d < 32; d <<= 1) {
            unsigned v = __shfl_up_sync(0xffffffffu, inc, d);
            if (tid >= d) inc += v;
        }
        unsigned run = inc - sum;   // lane-exclusive offset
        for (int j = 0; j < 64; j++) {
            const unsigned c = cnt[base + j];
            cnt[base + j] = run;
            run += c;
        }
    }
    __syncthreads();

    for (int i = tid; i < BN; i += 1024) {
        const unsigned pos = atomicAdd(&cnt[s_key[i]], 1u);
        g_order[pos] = (unsigned)i;
    }

    if (tid == 0) g_ctr = ctr_init;
}

// ---------------- main: 1 CTA/SM, chunked consumption of sorted ROIs --------
__global__ __launch_bounds__(512, 1)
void roi_align_kernel(const float* __restrict__ f0,
                      const float* __restrict__ f1,
                      const float* __restrict__ f2,
                      const float* __restrict__ f3,
                      const float* __restrict__ props,
                      float* __restrict__ out,
                      int BN, int N)
{
    __shared__ int4   s_off[NPOS];   // byte offsets of tl, tr, bl, br
    __shared__ float2 s_w[NPOS];     // (lx, ly)
    __shared__ unsigned s_base;

    const int tid   = threadIdx.x;
    const int c16   = (tid & 63) << 4;   // byte offset in channel dim
    const int pbase = tid >> 6;          // 0..7 position groups

    unsigned base = blockIdx.x * CHUNK;
    while (base < (unsigned)BN) {
        const unsigned end = min(base + (unsigned)CHUNK, (unsigned)BN);

        for (unsigned r = base; r < end; ++r) {
            const int roi = (int)g_order[r];
            const int b   = roi / N;

            const float4 box = reinterpret_cast<const float4*>(props)[roi];
            const float x1 = box.x, y1 = box.y, x2 = box.z, y2 = box.w;

            const int lvl = level_of(x1, y1, x2, y2);
            const int H = 256 >> lvl;
            const int W = 256 >> lvl;
            const float* f = (lvl == 0) ? f0 : (lvl == 1) ? f1
                            : (lvl == 2) ? f2 : f3;
            const char* fbb = (const char*)(f + (size_t)b * H * W * C_CH);

            if (tid < NPOS) {
                const int p  = tid;
                const int py = p / POOL;
                const int px = p - py * POOL;

                const float Hf = (float)H - 1.0f;
                const float Wf = (float)W - 1.0f;

                const float in_y = y1 * Hf + (float)py * ((y2 - y1) * Hf / (float)(POOL - 1));
                const float in_x = x1 * Wf + (float)px * ((x2 - x1) * Wf / (float)(POOL - 1));

                const float tyf = floorf(in_y);
                const float txf = floorf(in_x);

                const int tyi = (int)tyf;
                const int txi = (int)txf;
                const int yT = min(max(tyi,     0), H - 1);
                const int yB = min(max(tyi + 1, 0), H - 1);
                const int xL = min(max(txi,     0), W - 1);
                const int xR = min(max(txi + 1, 0), W - 1);

                const int rT = yT * W;
                const int rB = yB * W;
                int4 o;
                o.x = (rT + xL) << 10;   // tl (pixel stride = C*4 = 1024 B)
                o.y = (rT + xR) << 10;   // tr
                o.z = (rB + xL) << 10;   // bl
                o.w = (rB + xR) << 10;   // br
                s_off[p] = o;
                s_w[p] = make_float2(in_x - txf, in_y - tyf);
            }
            __syncthreads();

            char* out_roi = (char*)(out + (size_t)roi * (NPOS * C_CH)) + c16;

            #pragma unroll 2
            for (int p = pbase; p < NPOS; p += 8) {
                const int4   o = s_off[p];
                const float2 w = s_w[p];
                const float lx = w.x, ly = w.y;

                const float4 tl = *reinterpret_cast<const float4*>(fbb + o.x + c16);
                const float4 tr = *reinterpret_cast<const float4*>(fbb + o.y + c16);
                const float4 bl = *reinterpret_cast<const float4*>(fbb + o.z + c16);
                const float4 br = *reinterpret_cast<const float4*>(fbb + o.w + c16);

                float4 res;
                {
                    const float top = tl.x + (tr.x - tl.x) * lx;
                    const float bot = bl.x + (br.x - bl.x) * lx;
                    res.x = top + (bot - top) * ly;
                }
                {
                    const float top = tl.y + (tr.y - tl.y) * lx;
                    const float bot = bl.y + (br.y - bl.y) * lx;
                    res.y = top + (bot - top) * ly;
                }
                {
                    const float top = tl.z + (tr.z - tl.z) * lx;
                    const float bot = bl.z + (br.z - bl.z) * lx;
                    res.z = top + (bot - top) * ly;
                }
                {
                    const float top = tl.w + (tr.w - tl.w) * lx;
                    const float bot = bl.w + (br.w - bl.w) * lx;
                    res.w = top + (bot - top) * ly;
                }

                *reinterpret_cast<float4*>(out_roi + (p << 10)) = res;
            }
            __syncthreads();   // protect s_off/s_w before next ROI's setup
        }

        if (tid == 0) s_base = atomicAdd(&g_ctr, (unsigned)CHUNK);
        __syncthreads();
        base = s_base;
    }
}

extern "C" void kernel_launch(void* const* d_in, const int* in_sizes, int n_in,
                              void* d_out, int out_size)
{
    const float* f0    = (const float*)d_in[0];
    const float* f1    = (const float*)d_in[1];
    const float* f2    = (const float*)d_in[2];
    const float* f3    = (const float*)d_in[3];
    const float* props = (const float*)d_in[4];
    float* out = (float*)d_out;

    const int BN = in_sizes[4] / 4;                     // B*N rois
    const int B  = in_sizes[0] / (256 * 256 * 256);     // batch from feat0
    const int N  = (B > 0) ? (BN / B) : BN;

    const int nchunks = (BN + CHUNK - 1) / CHUNK;
    const int grid    = (nchunks < NSM) ? nchunks : NSM;
    const unsigned ctr_init = (unsigned)grid * CHUNK;

    sort_kernel<<<1, 1024>>>(props, BN, N, ctr_init);
    roi_align_kernel<<<grid, 512>>>(f0, f1, f2, f3, props, out, BN, N);
}